// round 13
// baseline (speedup 1.0000x reference)
#include <cuda_runtime.h>
#include <math.h>
#include <cstdint>

#define NTOK 512
#define H    12
#define CZ   128
#define CS   384
#define CATD 2112   // 192 + 96*4 + 1536
#define NOUT 1152   // packed projection width: Wq 192 | Wkv 384 | Wqp 144 | Wkvp 432

// ---------------- scratch (device globals) ----------------
__device__ float g_q   [NTOK * 192];         // [n][h*16+c]
__device__ float g_qpts[NTOK * 144];         // [n][(h*4+p)*3 + x]  (global frame)
__device__ float g_ck  [12 * 30 * NTOK];     // [h][d][n] d: 0-15 k, 16-27 kpts, 28 mask
__device__ float g_vall[12 * 40 * NTOK];     // [h][d][n] d: 0-15 v, 16-39 vpts
__device__ float g_cat [NTOK * CATD];
__device__ float g_wbt [12 * 132];           // c2*Wb^T [h][kk] (holes zero)
__device__ float g_ccn [12];                 // c2*bb
__device__ float g_wpack[CS * NOUT];         // [k][o] packed weights
__device__ float g_bpack[NOUT];              // packed bias
__device__ float g_raw [NTOK * NOUT];        // raw projections

// ---------------- cp.async helpers ----------------
__device__ __forceinline__ void cpasync16(unsigned int dst, const void* src) {
    asm volatile("cp.async.ca.shared.global [%0], [%1], 16;" :: "r"(dst), "l"(src));
}
__device__ __forceinline__ void cpasync_commit() {
    asm volatile("cp.async.commit_group;");
}
template <int N>
__device__ __forceinline__ void cpasync_wait() {
    asm volatile("cp.async.wait_group %0;" :: "n"(N));
}

// =================================================================================
// Kernel P: pack weights/bias + c2*Wb^T + init out=bout  (1728 blocks x 256)
// =================================================================================
__global__ __launch_bounds__(256) void pack_kernel(
    const float* __restrict__ Wq, const float* __restrict__ bq,
    const float* __restrict__ Wkv,const float* __restrict__ bkv,
    const float* __restrict__ Wqp,const float* __restrict__ bqp,
    const float* __restrict__ Wkvp,const float* __restrict__ bkvp,
    const float* __restrict__ Wb, const float* __restrict__ bb,
    const float* __restrict__ bout, float* __restrict__ out)
{
    const int idx = blockIdx.x * 256 + threadIdx.x;
    const float c2 = 0.57735026918962584f;   // 1/sqrt(3)
    if (idx < CS * NOUT) {
        int k = idx / NOUT, o = idx - k * NOUT;
        float v;
        if      (o < 192) v = Wq  [k*192 + o];
        else if (o < 576) v = Wkv [k*384 + o - 192];
        else if (o < 720) v = Wqp [k*144 + o - 576];
        else              v = Wkvp[k*432 + o - 720];
        g_wpack[idx] = v;
    }
    if (idx < NOUT) {
        int o = idx; float v;
        if      (o < 192) v = bq  [o];
        else if (o < 576) v = bkv [o - 192];
        else if (o < 720) v = bqp [o - 576];
        else              v = bkvp[o - 720];
        g_bpack[o] = v;
    }
    if (idx < 12 * 132) {
        int h = idx / 132, kk = idx - h * 132;
        g_wbt[idx] = (kk < 128) ? c2 * Wb[kk*12 + h] : 0.f;
    }
    if (idx < 12) g_ccn[idx] = c2 * bb[idx];
    if (idx < NTOK * 384) {
        out[idx] = bout[idx % 384];
    }
}

// =================================================================================
// Kernel A1: projection SGEMM  g_raw = s @ g_wpack + g_bpack
// =================================================================================
__global__ __launch_bounds__(256) void sgemm_kernel(const float* __restrict__ s)
{
    __shared__ float ash[16 * 68];   // [kk][mm]
    __shared__ float bsh[16 * 68];   // [kk][nn]
    const int bm = blockIdx.x & 7, bn = blockIdx.x >> 3;
    const int m0 = bm * 64, n0 = bn * 64;
    const int tid = threadIdx.x;
    const int tx = tid & 15, ty = tid >> 4;

    float pa[4], pb[4];
    #pragma unroll
    for (int r = 0; r < 4; r++) {
        int idx = tid + 256*r;
        int mm = idx >> 4, kk = idx & 15;
        pa[r] = s[(m0 + mm)*CS + kk];
        int nn = idx & 63, kk2 = idx >> 6;
        pb[r] = g_wpack[kk2*NOUT + n0 + nn];
    }

    float acc[4][4];
    {
        float4 bv = *(const float4*)(g_bpack + n0 + tx*4);
        #pragma unroll
        for (int mi = 0; mi < 4; mi++) {
            acc[mi][0] = bv.x; acc[mi][1] = bv.y; acc[mi][2] = bv.z; acc[mi][3] = bv.w;
        }
    }

    for (int k0 = 0; k0 < CS; k0 += 16) {
        __syncthreads();
        #pragma unroll
        for (int r = 0; r < 4; r++) {
            int idx = tid + 256*r;
            ash[(idx & 15)*68 + (idx >> 4)] = pa[r];
            bsh[(idx >> 6)*68 + (idx & 63)] = pb[r];
        }
        __syncthreads();
        if (k0 + 16 < CS) {
            #pragma unroll
            for (int r = 0; r < 4; r++) {
                int idx = tid + 256*r;
                int mm = idx >> 4, kk = idx & 15;
                pa[r] = s[(m0 + mm)*CS + k0 + 16 + kk];
                int nn = idx & 63, kk2 = idx >> 6;
                pb[r] = g_wpack[(k0 + 16 + kk2)*NOUT + n0 + nn];
            }
        }
        #pragma unroll
        for (int kk = 0; kk < 16; kk++) {
            float4 a4 = *(const float4*)(ash + kk*68 + ty*4);
            float4 b4 = *(const float4*)(bsh + kk*68 + tx*4);
            acc[0][0] += a4.x*b4.x; acc[0][1] += a4.x*b4.y; acc[0][2] += a4.x*b4.z; acc[0][3] += a4.x*b4.w;
            acc[1][0] += a4.y*b4.x; acc[1][1] += a4.y*b4.y; acc[1][2] += a4.y*b4.z; acc[1][3] += a4.y*b4.w;
            acc[2][0] += a4.z*b4.x; acc[2][1] += a4.z*b4.y; acc[2][2] += a4.z*b4.z; acc[2][3] += a4.z*b4.w;
            acc[3][0] += a4.w*b4.x; acc[3][1] += a4.w*b4.y; acc[3][2] += a4.w*b4.z; acc[3][3] += a4.w*b4.w;
        }
    }
    #pragma unroll
    for (int mi = 0; mi < 4; mi++) {
        float4 o4; o4.x = acc[mi][0]; o4.y = acc[mi][1]; o4.z = acc[mi][2]; o4.w = acc[mi][3];
        *(float4*)(g_raw + (size_t)(m0 + ty*4 + mi)*NOUT + n0 + tx*4) = o4;
    }
}

// =================================================================================
// Kernel A2: epilogue — rigid transform + scatter into j-major layouts.
// =================================================================================
__global__ __launch_bounds__(384) void epi_kernel(
    const float* __restrict__ tt, const float* __restrict__ tr, const float* __restrict__ msk)
{
    const int n0 = blockIdx.x * 4;
    const int t  = threadIdx.x;

    for (int m = 0; m < 4; m++) {
        const int n = n0 + m;
        const float* raw = g_raw + (size_t)n * NOUT;
        if (t < 192) {
            int h = t >> 4, c = t & 15;
            g_q[n*192 + t] = raw[t];
            g_ck  [(h*30 + c)*NTOK + n] = raw[192 + h*32 + c];        // k
            g_vall[(h*40 + c)*NTOK + n] = raw[192 + h*32 + 16 + c];   // v
        } else if (t < 240) {
            int p = t - 192;   // (h*4 + pq)
            float lx = raw[576 + p], ly = raw[576 + 48 + p], lz = raw[576 + 96 + p];
            const float* R = tr + n*9; const float* T = tt + n*3;
            float gx = R[0]*lx + R[1]*ly + R[2]*lz + T[0];
            float gy = R[3]*lx + R[4]*ly + R[5]*lz + T[1];
            float gz = R[6]*lx + R[7]*ly + R[8]*lz + T[2];
            g_qpts[n*144 + p*3 + 0] = gx;
            g_qpts[n*144 + p*3 + 1] = gy;
            g_qpts[n*144 + p*3 + 2] = gz;
        } else {
            int p = t - 240;   // (h*12 + pp)
            float lx = raw[720 + p], ly = raw[720 + 144 + p], lz = raw[720 + 288 + p];
            const float* R = tr + n*9; const float* T = tt + n*3;
            float gx = R[0]*lx + R[1]*ly + R[2]*lz + T[0];
            float gy = R[3]*lx + R[4]*ly + R[5]*lz + T[1];
            float gz = R[6]*lx + R[7]*ly + R[8]*lz + T[2];
            int h = p / 12, pp = p - h*12;
            if (pp < 4) {
                int d = 16 + pp*3;
                g_ck[(h*30 + d + 0)*NTOK + n] = gx;
                g_ck[(h*30 + d + 1)*NTOK + n] = gy;
                g_ck[(h*30 + d + 2)*NTOK + n] = gz;
            } else {
                int d = 16 + (pp - 4)*3;
                g_vall[(h*40 + d + 0)*NTOK + n] = gx;
                g_vall[(h*40 + d + 1)*NTOK + n] = gy;
                g_vall[(h*40 + d + 2)*NTOK + n] = gz;
            }
        }
    }
    if (t < 4) {
        int n = n0 + t;
        float mv = msk[n];
        #pragma unroll
        for (int h = 0; h < 12; h++)
            g_ck[(h*30 + 28)*NTOK + n] = mv;
    }
}

// =================================================================================
// Kernel B: fused attention (R10 structure; ONLY phase-3c changed to z-read-once).
// One block per query row i. ~100KB dyn smem, 2/SM.
// =================================================================================
#define ASHO 0                 // a[12][512]                       6144
#define ZSHO 6144              // z ping-pong 2x[64][132]=16896; later: part[12*1536=18432]
#define WBTO 23040             // c2*Wb^T [12][132]                1584
#define CQSO 24624             // cq [12][32]                      384
#define CCNO 25008             // cconst[12]
#define SMEM_FLOATS 25024
#define SMEM_BYTES  (SMEM_FLOATS * 4)

__global__ __launch_bounds__(384) void attn_kernel(
    const float* __restrict__ z,   const float* __restrict__ msk,
    const float* __restrict__ hwts,const float* __restrict__ tt,
    const float* __restrict__ tr)
{
    extern __shared__ float sm[];
    float* a_sh = sm + ASHO;
    float* zsh  = sm + ZSHO;
    float* wbt  = sm + WBTO;
    float* cqs  = sm + CQSO;
    float* ccn  = sm + CCNO;

    const int i = blockIdx.x, t = threadIdx.x;
    const float mask_i = msk[i];

    // ---- build cq / cconst / wbt ----
    for (int idx = t; idx < 360; idx += 384) {
        int h = idx / 30, d = idx - h*30;
        float x = hwts[h];
        float sp = (x > 20.f) ? x : log1pf(__expf(x));
        float hw = sp * 0.13608276348795434f;   // softplus * sqrt(1/54)
        float v;
        if      (d < 16)  v = 0.14433756729740643f * g_q[i*192 + h*16 + d]; // 1/sqrt(48)
        else if (d < 28)  v = g_qpts[i*144 + h*12 + (d - 16)];              // raw q_pts
        else if (d == 28) v = -0.5f * hw;
        else              v = mask_i;
        cqs[h*32 + d] = v;
    }
    if (t < 12) ccn[t] = g_ccn[t];
    for (int idx = t; idx < 1584; idx += 384)
        wbt[idx] = g_wbt[idx];
    __syncthreads();

    const size_t zbase = (size_t)i * NTOK * CZ;
    const unsigned int zsh_s = (unsigned int)__cvta_generic_to_shared(zsh);
    const int w = t >> 5, lane = t & 31;

    // ---- Phase 1: bias GEMM with cp.async double-buffered 64-row chunks (R10 map) ----
    {
        const int ks = t & 7, g = t >> 3;         // 8 k-splits, 48 groups
        const int hg = g % 3, jq = g / 3;         // jq 0..15, hg: 4-head group

        // stage chunk 0 into buf 0
        for (int idx = t; idx < 2048; idx += 384) {
            int r = idx >> 5, c4 = idx & 31;
            cpasync16(zsh_s + (r*132 + c4*4)*4, z + zbase + (size_t)r*128 + c4*4);
        }
        cpasync_commit();

        for (int c = 0; c < 8; c++) {
            const float* curbuf = zsh + (c & 1) * 8448;
            if (c < 7) {
                const unsigned int nb_s = zsh_s + (((c + 1) & 1) * 8448) * 4;
                const int j0n = (c + 1) * 64;
                for (int idx = t; idx < 2048; idx += 384) {
                    int r = idx >> 5, c4 = idx & 31;
                    cpasync16(nb_s + (r*132 + c4*4)*4, z + zbase + (size_t)(j0n + r)*128 + c4*4);
                }
                cpasync_commit();
                cpasync_wait<1>();
            } else {
                cpasync_wait<0>();
            }
            __syncthreads();

            const int j0 = c * 64;
            float acc[4][4];
            #pragma unroll
            for (int a = 0; a < 4; a++)
                #pragma unroll
                for (int b = 0; b < 4; b++) acc[a][b] = 0.f;
            #pragma unroll
            for (int it = 0; it < 4; it++) {
                const int kq = it*8 + ks;
                float4 z4[4], w4[4];
                #pragma unroll
                for (int jj = 0; jj < 4; jj++)
                    z4[jj] = *(const float4*)(curbuf + (jq*4 + jj)*132 + kq*4);
                #pragma unroll
                for (int hh = 0; hh < 4; hh++)
                    w4[hh] = *(const float4*)(wbt + (hg*4 + hh)*132 + kq*4);
                #pragma unroll
                for (int jj = 0; jj < 4; jj++)
                    #pragma unroll
                    for (int hh = 0; hh < 4; hh++) {
                        acc[jj][hh] += z4[jj].x * w4[hh].x;
                        acc[jj][hh] += z4[jj].y * w4[hh].y;
                        acc[jj][hh] += z4[jj].z * w4[hh].z;
                        acc[jj][hh] += z4[jj].w * w4[hh].w;
                    }
            }
            #pragma unroll
            for (int jj = 0; jj < 4; jj++)
                #pragma unroll
                for (int hh = 0; hh < 4; hh++) {
                    float v = acc[jj][hh];
                    v += __shfl_xor_sync(0xffffffffu, v, 1);
                    v += __shfl_xor_sync(0xffffffffu, v, 2);
                    v += __shfl_xor_sync(0xffffffffu, v, 4);
                    if (ks == 0)
                        a_sh[(hg*4 + hh)*512 + j0 + jq*4 + jj] = v;
                }
            __syncthreads();
        }
    }

    // ---- Phase 1b: add qk + point-dist (direct (q-k)^2) + mask ----
    {
        float cq[16], qp[12];
        #pragma unroll
        for (int d = 0; d < 16; d++) cq[d] = cqs[w*32 + d];
        #pragma unroll
        for (int p = 0; p < 12; p++) qp[p] = cqs[w*32 + 16 + p];
        const float nh = cqs[w*32 + 28];          // -0.5*hw
        const float mi = cqs[w*32 + 29];          // mask_i
        const float cst = ccn[w];
        #pragma unroll
        for (int r = 0; r < 4; r++) {
            const int j = r*128 + lane*4;
            const float* ckb = g_ck + (size_t)w*30*NTOK + j;
            float4 av; av.x = cst; av.y = cst; av.z = cst; av.w = cst;
            #pragma unroll
            for (int d = 0; d < 16; d++) {
                float4 kv = *(const float4*)(ckb + d*NTOK);
                av.x += cq[d]*kv.x; av.y += cq[d]*kv.y;
                av.z += cq[d]*kv.z; av.w += cq[d]*kv.w;
            }
            float4 d2; d2.x = d2.y = d2.z = d2.w = 0.f;
            #pragma unroll
            for (int p = 0; p < 12; p++) {
                float4 kv = *(const float4*)(ckb + (16 + p)*NTOK);
                float dx = qp[p] - kv.x; d2.x += dx*dx;
                float dy = qp[p] - kv.y; d2.y += dy*dy;
                float dz = qp[p] - kv.z; d2.z += dz*dz;
                float dw = qp[p] - kv.w; d2.w += dw*dw;
            }
            av.x += nh*d2.x; av.y += nh*d2.y; av.z += nh*d2.z; av.w += nh*d2.w;
            float4 mj = *(const float4*)(ckb + 28*NTOK);
            av.x += 100000.0f * fmaf(mi, mj.x, -1.0f);
            av.y += 100000.0f * fmaf(mi, mj.y, -1.0f);
            av.z += 100000.0f * fmaf(mi, mj.z, -1.0f);
            av.w += 100000.0f * fmaf(mi, mj.w, -1.0f);
            float4 cur = *(const float4*)(a_sh + w*512 + j);
            cur.x += av.x; cur.y += av.y; cur.z += av.z; cur.w += av.w;
            *(float4*)(a_sh + w*512 + j) = cur;
        }
    }
    __syncthreads();

    // ---- Phase 2: softmax (warp w -> head w) ----
    {
        float* row = a_sh + w * 512;
        float mx = -1e30f;
        for (int j = lane; j < 512; j += 32) mx = fmaxf(mx, row[j]);
        #pragma unroll
        for (int o = 16; o; o >>= 1) mx = fmaxf(mx, __shfl_xor_sync(0xffffffffu, mx, o));
        float ssum = 0.f;
        for (int j = lane; j < 512; j += 32) { float e = __expf(row[j] - mx); row[j] = e; ssum += e; }
        #pragma unroll
        for (int o = 16; o; o >>= 1) ssum += __shfl_xor_sync(0xffffffffu, ssum, o);
        float inv = 1.0f / ssum;
        for (int j = lane; j < 512; j += 32) row[j] *= inv;
    }
    __syncthreads();

    // ---- Phase 3a: o and raw o_pt — 4 outputs per warp-task ----
    {
        float* optbuf = zsh;                       // 288 floats (z dead)
        #pragma unroll 2
        for (int r = 0; r < 10; r++) {
            const int task = r*12 + w;             // 120 tasks
            const int h = task / 10, dq = (task - h*10) * 4;
            const float* vb = g_vall + (size_t)(h*40 + dq)*NTOK;
            const float* ab = a_sh + h*512;
            float4 acc0, acc1, acc2, acc3;
            acc0.x=acc0.y=acc0.z=acc0.w=0.f; acc1=acc0; acc2=acc0; acc3=acc0;
            #pragma unroll
            for (int it = 0; it < 4; it++) {
                const int j = it*128 + lane*4;
                float4 a4 = *(const float4*)(ab + j);
                float4 v0 = *(const float4*)(vb + 0*NTOK + j);
                float4 v1 = *(const float4*)(vb + 1*NTOK + j);
                float4 v2 = *(const float4*)(vb + 2*NTOK + j);
                float4 v3 = *(const float4*)(vb + 3*NTOK + j);
                acc0.x += a4.x*v0.x; acc0.y += a4.y*v0.y; acc0.z += a4.z*v0.z; acc0.w += a4.w*v0.w;
                acc1.x += a4.x*v1.x; acc1.y += a4.y*v1.y; acc1.z += a4.z*v1.z; acc1.w += a4.w*v1.w;
                acc2.x += a4.x*v2.x; acc2.y += a4.y*v2.y; acc2.z += a4.z*v2.z; acc2.w += a4.w*v2.w;
                acc3.x += a4.x*v3.x; acc3.y += a4.y*v3.y; acc3.z += a4.z*v3.z; acc3.w += a4.w*v3.w;
            }
            float s0 = acc0.x + acc0.y + acc0.z + acc0.w;
            float s1 = acc1.x + acc1.y + acc1.z + acc1.w;
            float s2 = acc2.x + acc2.y + acc2.z + acc2.w;
            float s3 = acc3.x + acc3.y + acc3.z + acc3.w;
            #pragma unroll
            for (int o = 16; o; o >>= 1) {
                s0 += __shfl_xor_sync(0xffffffffu, s0, o);
                s1 += __shfl_xor_sync(0xffffffffu, s1, o);
                s2 += __shfl_xor_sync(0xffffffffu, s2, o);
                s3 += __shfl_xor_sync(0xffffffffu, s3, o);
            }
            if (lane == 0) {
                float res[4] = {s0, s1, s2, s3};
                #pragma unroll
                for (int dd = 0; dd < 4; dd++) {
                    int d = dq + dd;
                    if (d < 16) g_cat[i*CATD + h*16 + d] = res[dd];
                    else        optbuf[h*24 + (d - 16)] = res[dd];
                }
            }
        }
    }
    __syncthreads();

    // ---- Phase 3b: inverse rigid transform + norms ----
    if (t < 96) {
        const float* optbuf = zsh;
        float gx = optbuf[t*3], gy = optbuf[t*3 + 1], gz = optbuf[t*3 + 2];
        const float* R = tr + i*9; const float* T = tt + i*3;
        float dx = gx - T[0], dy = gy - T[1], dz = gz - T[2];
        float lx = R[0]*dx + R[3]*dy + R[6]*dz;
        float ly = R[1]*dx + R[4]*dy + R[7]*dz;
        float lz = R[2]*dx + R[5]*dy + R[8]*dz;
        float* cr = g_cat + i*CATD;
        cr[192 + t] = lx; cr[288 + t] = ly; cr[384 + t] = lz;
        cr[480 + t] = sqrtf(lx*lx + ly*ly + lz*lz + 1e-8f);
    }

    // ---- Phase 3c: o_pair — each z row read ONCE per CTA.
    //      warp = j-quad stripe; each warp accumulates ALL 12 heads. ----
    {
        float acc[12][4];
        #pragma unroll
        for (int h = 0; h < 12; h++)
            #pragma unroll
            for (int cc = 0; cc < 4; cc++) acc[h][cc] = 0.f;

        for (int qd = w; qd < 128; qd += 12) {
            const int j = qd * 4;
            float4 z4[4];
            #pragma unroll
            for (int jj = 0; jj < 4; jj++)
                z4[jj] = *(const float4*)(z + zbase + (size_t)(j + jj)*128 + lane*4);
            #pragma unroll
            for (int h = 0; h < 12; h++) {
                float4 a4 = *(const float4*)(a_sh + h*512 + j);   // broadcast LDS
                acc[h][0] += a4.x*z4[0].x + a4.y*z4[1].x + a4.z*z4[2].x + a4.w*z4[3].x;
                acc[h][1] += a4.x*z4[0].y + a4.y*z4[1].y + a4.z*z4[2].y + a4.w*z4[3].y;
                acc[h][2] += a4.x*z4[0].z + a4.y*z4[1].z + a4.z*z4[2].z + a4.w*z4[3].z;
                acc[h][3] += a4.x*z4[0].w + a4.y*z4[1].w + a4.z*z4[2].w + a4.w*z4[3].w;
            }
        }
        __syncthreads();                           // protect 3b's optbuf reads
        float* part = zsh;                         // [12w][12h*128c] = 18432 <= 18880 avail
        #pragma unroll
        for (int h = 0; h < 12; h++) {
            float4 o4; o4.x = acc[h][0]; o4.y = acc[h][1]; o4.z = acc[h][2]; o4.w = acc[h][3];
            *(float4*)(part + w*1536 + h*128 + lane*4) = o4;
        }
    }
    __syncthreads();
    {
        const float* part = zsh;
        for (int idx = t; idx < 1536; idx += 384) {
            float v = 0.f;
            #pragma unroll
            for (int ww = 0; ww < 12; ww++) v += part[ww*1536 + idx];
            g_cat[i*CATD + 576 + idx] = v;
        }
    }
}

// =================================================================================
// Kernel C1: out += cat @ Wout as tiled SGEMM. 64x64 tiles, BK=16,
// k-split 11 (192 each): grid = 8m x 6n x 11k = 528 blocks, 256 threads.
// =================================================================================
__global__ __launch_bounds__(256) void out_gemm_kernel(
    const float* __restrict__ Wout, float* __restrict__ out)
{
    __shared__ float ash[16 * 68];   // [kk][mm]
    __shared__ float bsh[16 * 68];   // [kk][nn]
    const int bx = blockIdx.x;
    const int ksp = bx / 48, rem = bx - ksp * 48;
    const int bm = rem & 7, bn = rem >> 3;
    const int m0 = bm * 64, n0 = bn * 64, kbase = ksp * 192;
    const int tid = threadIdx.x;
    const int tx = tid & 15, ty = tid >> 4;

    float pa[4], pb[4];
    #pragma unroll
    for (int r = 0; r < 4; r++) {
        int idx = tid + 256*r;
        int mm = idx >> 4, kk = idx & 15;
        pa[r] = g_cat[(size_t)(m0 + mm)*CATD + kbase + kk];
        int nn = idx & 63, kk2 = idx >> 6;
        pb[r] = Wout[(size_t)(kbase + kk2)*384 + n0 + nn];
    }

    float acc[4][4];
    #pragma unroll
    for (int a = 0; a < 4; a++)
        #pragma unroll
        for (int b = 0; b < 4; b++) acc[a][b] = 0.f;

    for (int k0 = 0; k0 < 192; k0 += 16) {
        __syncthreads();
        #pragma unroll
        for (int r = 0; r < 4; r++) {
            int idx = tid + 256*r;
            ash[(idx & 15)*68 + (idx >> 4)] = pa[r];
            bsh[(idx >> 6)*68 + (idx & 63)] = pb[r];
        }
        __syncthreads();
        if (k0 + 16 < 192) {
            #pragma unroll
            for (int r = 0; r < 4; r++) {
                int idx = tid + 256*r;
                int mm = idx >> 4, kk = idx & 15;
                pa[r] = g_cat[(size_t)(m0 + mm)*CATD + kbase + k0 + 16 + kk];
                int nn = idx & 63, kk2 = idx >> 6;
                pb[r] = Wout[(size_t)(kbase + k0 + 16 + kk2)*384 + n0 + nn];
            }
        }
        #pragma unroll
        for (int kk = 0; kk < 16; kk++) {
            float4 a4 = *(const float4*)(ash + kk*68 + ty*4);
            float4 b4 = *(const float4*)(bsh + kk*68 + tx*4);
            acc[0][0] += a4.x*b4.x; acc[0][1] += a4.x*b4.y; acc[0][2] += a4.x*b4.z; acc[0][3] += a4.x*b4.w;
            acc[1][0] += a4.y*b4.x; acc[1][1] += a4.y*b4.y; acc[1][2] += a4.y*b4.z; acc[1][3] += a4.y*b4.w;
            acc[2][0] += a4.z*b4.x; acc[2][1] += a4.z*b4.y; acc[2][2] += a4.z*b4.z; acc[2][3] += a4.z*b4.w;
            acc[3][0] += a4.w*b4.x; acc[3][1] += a4.w*b4.y; acc[3][2] += a4.w*b4.z; acc[3][3] += a4.w*b4.w;
        }
    }
    #pragma unroll
    for (int mi = 0; mi < 4; mi++) {
        float* op = out + (size_t)(m0 + ty*4 + mi)*384 + n0 + tx*4;
        atomicAdd(op + 0, acc[mi][0]);
        atomicAdd(op + 1, acc[mi][1]);
        atomicAdd(op + 2, acc[mi][2]);
        atomicAdd(op + 3, acc[mi][3]);
    }
}

// =================================================================================
extern "C" void kernel_launch(void* const* d_in, const int* in_sizes, int n_in,
                              void* d_out, int out_size)
{
    (void)in_sizes; (void)n_in; (void)out_size;
    const float* s    = (const float*)d_in[0];
    const float* z    = (const float*)d_in[1];
    const float* tt   = (const float*)d_in[2];
    const float* tr   = (const float*)d_in[3];
    const float* mask = (const float*)d_in[4];
    const float* Wq   = (const float*)d_in[5];
    const float* bq   = (const float*)d_in[6];
    const float* Wkv  = (const float*)d_in[7];
    const float* bkv  = (const float*)d_in[8];
    const float* Wqp  = (const float*)d_in[9];
    const float* bqp  = (const float*)d_in[10];
    const float* Wkvp = (const float*)d_in[11];
    const float* bkvp = (const float*)d_in[12];
    const float* Wb   = (const float*)d_in[13];
    const float* bb   = (const float*)d_in[14];
    const float* hwts = (const float*)d_in[15];
    const float* Wout = (const float*)d_in[16];
    const float* bout = (const float*)d_in[17];
    float* out = (float*)d_out;

    cudaFuncSetAttribute(attn_kernel, cudaFuncAttributeMaxDynamicSharedMemorySize, SMEM_BYTES);

    // attn stays at launch index 3 for the ncu capture
    pack_kernel<<<1728, 256>>>(Wq, bq, Wkv, bkv, Wqp, bqp, Wkvp, bkvp, Wb, bb, bout, out);
    sgemm_kernel<<<144, 256>>>(s);
    epi_kernel<<<128, 384>>>(tt, tr, mask);
    attn_kernel<<<512, 384, SMEM_BYTES>>>(z, mask, hwts, tt, tr);
    out_gemm_kernel<<<528, 256>>>(Wout, out);
}

// round 14
// speedup vs baseline: 1.0469x; 1.0469x over previous
#include <cuda_runtime.h>
#include <math.h>
#include <cstdint>

#define NTOK 512
#define H    12
#define CZ   128
#define CS   384
#define CATD 2112   // 192 + 96*4 + 1536
#define NOUT 1152   // packed projection width: Wq 192 | Wkv 384 | Wqp 144 | Wkvp 432

// ---------------- scratch (device globals) ----------------
__device__ float g_q   [NTOK * 192];         // [n][h*16+c]
__device__ float g_qpts[NTOK * 144];         // [n][(h*4+p)*3 + x]  (global frame)
__device__ float g_ck  [12 * 30 * NTOK];     // [h][d][n] d: 0-15 k, 16-27 kpts, 28 mask
__device__ float g_vall[12 * 40 * NTOK];     // [h][d][n] d: 0-15 v, 16-39 vpts
__device__ float g_cat [NTOK * CATD];
__device__ float g_wbt [12 * 132];           // c2*Wb^T [h][kk] (holes zero)
__device__ float g_ccn [12];                 // c2*bb
__device__ float g_wpack[CS * NOUT];         // [k][o] packed weights
__device__ float g_bpack[NOUT];              // packed bias
__device__ float g_raw [NTOK * NOUT];        // raw projections

// ---------------- cp.async helpers ----------------
__device__ __forceinline__ void cpasync16(unsigned int dst, const void* src) {
    asm volatile("cp.async.ca.shared.global [%0], [%1], 16;" :: "r"(dst), "l"(src));
}
__device__ __forceinline__ void cpasync_commit() {
    asm volatile("cp.async.commit_group;");
}
template <int N>
__device__ __forceinline__ void cpasync_wait() {
    asm volatile("cp.async.wait_group %0;" :: "n"(N));
}

// =================================================================================
// Kernel P: pack weights/bias + c2*Wb^T + init out=bout  (1728 blocks x 256)
// =================================================================================
__global__ __launch_bounds__(256) void pack_kernel(
    const float* __restrict__ Wq, const float* __restrict__ bq,
    const float* __restrict__ Wkv,const float* __restrict__ bkv,
    const float* __restrict__ Wqp,const float* __restrict__ bqp,
    const float* __restrict__ Wkvp,const float* __restrict__ bkvp,
    const float* __restrict__ Wb, const float* __restrict__ bb,
    const float* __restrict__ bout, float* __restrict__ out)
{
    const int idx = blockIdx.x * 256 + threadIdx.x;
    const float c2 = 0.57735026918962584f;   // 1/sqrt(3)
    if (idx < CS * NOUT) {
        int k = idx / NOUT, o = idx - k * NOUT;
        float v;
        if      (o < 192) v = Wq  [k*192 + o];
        else if (o < 576) v = Wkv [k*384 + o - 192];
        else if (o < 720) v = Wqp [k*144 + o - 576];
        else              v = Wkvp[k*432 + o - 720];
        g_wpack[idx] = v;
    }
    if (idx < NOUT) {
        int o = idx; float v;
        if      (o < 192) v = bq  [o];
        else if (o < 576) v = bkv [o - 192];
        else if (o < 720) v = bqp [o - 576];
        else              v = bkvp[o - 720];
        g_bpack[o] = v;
    }
    if (idx < 12 * 132) {
        int h = idx / 132, kk = idx - h * 132;
        g_wbt[idx] = (kk < 128) ? c2 * Wb[kk*12 + h] : 0.f;
    }
    if (idx < 12) g_ccn[idx] = c2 * bb[idx];
    if (idx < NTOK * 384) {
        out[idx] = bout[idx % 384];
    }
}

// =================================================================================
// Kernel A1: projection SGEMM  g_raw = s @ g_wpack + g_bpack
// =================================================================================
__global__ __launch_bounds__(256) void sgemm_kernel(const float* __restrict__ s)
{
    __shared__ float ash[16 * 68];   // [kk][mm]
    __shared__ float bsh[16 * 68];   // [kk][nn]
    const int bm = blockIdx.x & 7, bn = blockIdx.x >> 3;
    const int m0 = bm * 64, n0 = bn * 64;
    const int tid = threadIdx.x;
    const int tx = tid & 15, ty = tid >> 4;

    float pa[4], pb[4];
    #pragma unroll
    for (int r = 0; r < 4; r++) {
        int idx = tid + 256*r;
        int mm = idx >> 4, kk = idx & 15;
        pa[r] = s[(m0 + mm)*CS + kk];
        int nn = idx & 63, kk2 = idx >> 6;
        pb[r] = g_wpack[kk2*NOUT + n0 + nn];
    }

    float acc[4][4];
    {
        float4 bv = *(const float4*)(g_bpack + n0 + tx*4);
        #pragma unroll
        for (int mi = 0; mi < 4; mi++) {
            acc[mi][0] = bv.x; acc[mi][1] = bv.y; acc[mi][2] = bv.z; acc[mi][3] = bv.w;
        }
    }

    for (int k0 = 0; k0 < CS; k0 += 16) {
        __syncthreads();
        #pragma unroll
        for (int r = 0; r < 4; r++) {
            int idx = tid + 256*r;
            ash[(idx & 15)*68 + (idx >> 4)] = pa[r];
            bsh[(idx >> 6)*68 + (idx & 63)] = pb[r];
        }
        __syncthreads();
        if (k0 + 16 < CS) {
            #pragma unroll
            for (int r = 0; r < 4; r++) {
                int idx = tid + 256*r;
                int mm = idx >> 4, kk = idx & 15;
                pa[r] = s[(m0 + mm)*CS + k0 + 16 + kk];
                int nn = idx & 63, kk2 = idx >> 6;
                pb[r] = g_wpack[(k0 + 16 + kk2)*NOUT + n0 + nn];
            }
        }
        #pragma unroll
        for (int kk = 0; kk < 16; kk++) {
            float4 a4 = *(const float4*)(ash + kk*68 + ty*4);
            float4 b4 = *(const float4*)(bsh + kk*68 + tx*4);
            acc[0][0] += a4.x*b4.x; acc[0][1] += a4.x*b4.y; acc[0][2] += a4.x*b4.z; acc[0][3] += a4.x*b4.w;
            acc[1][0] += a4.y*b4.x; acc[1][1] += a4.y*b4.y; acc[1][2] += a4.y*b4.z; acc[1][3] += a4.y*b4.w;
            acc[2][0] += a4.z*b4.x; acc[2][1] += a4.z*b4.y; acc[2][2] += a4.z*b4.z; acc[2][3] += a4.z*b4.w;
            acc[3][0] += a4.w*b4.x; acc[3][1] += a4.w*b4.y; acc[3][2] += a4.w*b4.z; acc[3][3] += a4.w*b4.w;
        }
    }
    #pragma unroll
    for (int mi = 0; mi < 4; mi++) {
        float4 o4; o4.x = acc[mi][0]; o4.y = acc[mi][1]; o4.z = acc[mi][2]; o4.w = acc[mi][3];
        *(float4*)(g_raw + (size_t)(m0 + ty*4 + mi)*NOUT + n0 + tx*4) = o4;
    }
}

// =================================================================================
// Kernel A2: epilogue — rigid transform + scatter into j-major layouts.
// =================================================================================
__global__ __launch_bounds__(384) void epi_kernel(
    const float* __restrict__ tt, const float* __restrict__ tr, const float* __restrict__ msk)
{
    const int n0 = blockIdx.x * 4;
    const int t  = threadIdx.x;

    for (int m = 0; m < 4; m++) {
        const int n = n0 + m;
        const float* raw = g_raw + (size_t)n * NOUT;
        if (t < 192) {
            int h = t >> 4, c = t & 15;
            g_q[n*192 + t] = raw[t];
            g_ck  [(h*30 + c)*NTOK + n] = raw[192 + h*32 + c];        // k
            g_vall[(h*40 + c)*NTOK + n] = raw[192 + h*32 + 16 + c];   // v
        } else if (t < 240) {
            int p = t - 192;   // (h*4 + pq)
            float lx = raw[576 + p], ly = raw[576 + 48 + p], lz = raw[576 + 96 + p];
            const float* R = tr + n*9; const float* T = tt + n*3;
            float gx = R[0]*lx + R[1]*ly + R[2]*lz + T[0];
            float gy = R[3]*lx + R[4]*ly + R[5]*lz + T[1];
            float gz = R[6]*lx + R[7]*ly + R[8]*lz + T[2];
            g_qpts[n*144 + p*3 + 0] = gx;
            g_qpts[n*144 + p*3 + 1] = gy;
            g_qpts[n*144 + p*3 + 2] = gz;
        } else {
            int p = t - 240;   // (h*12 + pp)
            float lx = raw[720 + p], ly = raw[720 + 144 + p], lz = raw[720 + 288 + p];
            const float* R = tr + n*9; const float* T = tt + n*3;
            float gx = R[0]*lx + R[1]*ly + R[2]*lz + T[0];
            float gy = R[3]*lx + R[4]*ly + R[5]*lz + T[1];
            float gz = R[6]*lx + R[7]*ly + R[8]*lz + T[2];
            int h = p / 12, pp = p - h*12;
            if (pp < 4) {
                int d = 16 + pp*3;
                g_ck[(h*30 + d + 0)*NTOK + n] = gx;
                g_ck[(h*30 + d + 1)*NTOK + n] = gy;
                g_ck[(h*30 + d + 2)*NTOK + n] = gz;
            } else {
                int d = 16 + (pp - 4)*3;
                g_vall[(h*40 + d + 0)*NTOK + n] = gx;
                g_vall[(h*40 + d + 1)*NTOK + n] = gy;
                g_vall[(h*40 + d + 2)*NTOK + n] = gz;
            }
        }
    }
    if (t < 4) {
        int n = n0 + t;
        float mv = msk[n];
        #pragma unroll
        for (int h = 0; h < 12; h++)
            g_ck[(h*30 + 28)*NTOK + n] = mv;
    }
}

// =================================================================================
// Kernel B: fused attention — EXACT R10 structure (best measured: 156us, regs 73).
// One block per query row i. ~100KB dyn smem, 2/SM.
// =================================================================================
#define ASHO 0                 // a[12][512]                       6144
#define ZSHO 6144              // z ping-pong 2x[64][132]=16896    (reused later)
#define WBTO 23040             // c2*Wb^T [12][132]                1584
#define CQSO 24624             // cq [12][32]                      384
#define CCNO 25008             // cconst[12]
#define SMEM_FLOATS 25024
#define SMEM_BYTES  (SMEM_FLOATS * 4)

__global__ __launch_bounds__(384) void attn_kernel(
    const float* __restrict__ z,   const float* __restrict__ msk,
    const float* __restrict__ hwts,const float* __restrict__ tt,
    const float* __restrict__ tr)
{
    extern __shared__ float sm[];
    float* a_sh = sm + ASHO;
    float* zsh  = sm + ZSHO;
    float* wbt  = sm + WBTO;
    float* cqs  = sm + CQSO;
    float* ccn  = sm + CCNO;

    const int i = blockIdx.x, t = threadIdx.x;
    const float mask_i = msk[i];

    // ---- build cq / cconst / wbt ----
    for (int idx = t; idx < 360; idx += 384) {
        int h = idx / 30, d = idx - h*30;
        float x = hwts[h];
        float sp = (x > 20.f) ? x : log1pf(__expf(x));
        float hw = sp * 0.13608276348795434f;   // softplus * sqrt(1/54)
        float v;
        if      (d < 16)  v = 0.14433756729740643f * g_q[i*192 + h*16 + d]; // 1/sqrt(48)
        else if (d < 28)  v = g_qpts[i*144 + h*12 + (d - 16)];              // raw q_pts
        else if (d == 28) v = -0.5f * hw;
        else              v = mask_i;
        cqs[h*32 + d] = v;
    }
    if (t < 12) ccn[t] = g_ccn[t];
    for (int idx = t; idx < 1584; idx += 384)
        wbt[idx] = g_wbt[idx];
    __syncthreads();

    const size_t zbase = (size_t)i * NTOK * CZ;
    const unsigned int zsh_s = (unsigned int)__cvta_generic_to_shared(zsh);
    const int w = t >> 5, lane = t & 31;

    // ---- Phase 1: bias GEMM with cp.async double-buffered 64-row chunks ----
    {
        const int ks = t & 7, g = t >> 3;         // 8 k-splits, 48 groups
        const int hg = g % 3, jq = g / 3;         // jq 0..15, hg: 4-head group

        // stage chunk 0 into buf 0
        for (int idx = t; idx < 2048; idx += 384) {
            int r = idx >> 5, c4 = idx & 31;
            cpasync16(zsh_s + (r*132 + c4*4)*4, z + zbase + (size_t)r*128 + c4*4);
        }
        cpasync_commit();

        for (int c = 0; c < 8; c++) {
            const float* curbuf = zsh + (c & 1) * 8448;
            if (c < 7) {
                const unsigned int nb_s = zsh_s + (((c + 1) & 1) * 8448) * 4;
                const int j0n = (c + 1) * 64;
                for (int idx = t; idx < 2048; idx += 384) {
                    int r = idx >> 5, c4 = idx & 31;
                    cpasync16(nb_s + (r*132 + c4*4)*4, z + zbase + (size_t)(j0n + r)*128 + c4*4);
                }
                cpasync_commit();
                cpasync_wait<1>();
            } else {
                cpasync_wait<0>();
            }
            __syncthreads();

            const int j0 = c * 64;
            float acc[4][4];
            #pragma unroll
            for (int a = 0; a < 4; a++)
                #pragma unroll
                for (int b = 0; b < 4; b++) acc[a][b] = 0.f;
            #pragma unroll
            for (int it = 0; it < 4; it++) {
                const int kq = it*8 + ks;
                float4 z4[4], w4[4];
                #pragma unroll
                for (int jj = 0; jj < 4; jj++)
                    z4[jj] = *(const float4*)(curbuf + (jq*4 + jj)*132 + kq*4);
                #pragma unroll
                for (int hh = 0; hh < 4; hh++)
                    w4[hh] = *(const float4*)(wbt + (hg*4 + hh)*132 + kq*4);
                #pragma unroll
                for (int jj = 0; jj < 4; jj++)
                    #pragma unroll
                    for (int hh = 0; hh < 4; hh++) {
                        acc[jj][hh] += z4[jj].x * w4[hh].x;
                        acc[jj][hh] += z4[jj].y * w4[hh].y;
                        acc[jj][hh] += z4[jj].z * w4[hh].z;
                        acc[jj][hh] += z4[jj].w * w4[hh].w;
                    }
            }
            #pragma unroll
            for (int jj = 0; jj < 4; jj++)
                #pragma unroll
                for (int hh = 0; hh < 4; hh++) {
                    float v = acc[jj][hh];
                    v += __shfl_xor_sync(0xffffffffu, v, 1);
                    v += __shfl_xor_sync(0xffffffffu, v, 2);
                    v += __shfl_xor_sync(0xffffffffu, v, 4);
                    if (ks == 0)
                        a_sh[(hg*4 + hh)*512 + j0 + jq*4 + jj] = v;
                }
            __syncthreads();
        }
    }

    // ---- Phase 1b: add qk + point-dist (direct (q-k)^2) + mask ----
    {
        float cq[16], qp[12];
        #pragma unroll
        for (int d = 0; d < 16; d++) cq[d] = cqs[w*32 + d];
        #pragma unroll
        for (int p = 0; p < 12; p++) qp[p] = cqs[w*32 + 16 + p];
        const float nh = cqs[w*32 + 28];          // -0.5*hw
        const float mi = cqs[w*32 + 29];          // mask_i
        const float cst = ccn[w];
        #pragma unroll
        for (int r = 0; r < 4; r++) {
            const int j = r*128 + lane*4;
            const float* ckb = g_ck + (size_t)w*30*NTOK + j;
            float4 av; av.x = cst; av.y = cst; av.z = cst; av.w = cst;
            #pragma unroll
            for (int d = 0; d < 16; d++) {
                float4 kv = *(const float4*)(ckb + d*NTOK);
                av.x += cq[d]*kv.x; av.y += cq[d]*kv.y;
                av.z += cq[d]*kv.z; av.w += cq[d]*kv.w;
            }
            float4 d2; d2.x = d2.y = d2.z = d2.w = 0.f;
            #pragma unroll
            for (int p = 0; p < 12; p++) {
                float4 kv = *(const float4*)(ckb + (16 + p)*NTOK);
                float dx = qp[p] - kv.x; d2.x += dx*dx;
                float dy = qp[p] - kv.y; d2.y += dy*dy;
                float dz = qp[p] - kv.z; d2.z += dz*dz;
                float dw = qp[p] - kv.w; d2.w += dw*dw;
            }
            av.x += nh*d2.x; av.y += nh*d2.y; av.z += nh*d2.z; av.w += nh*d2.w;
            float4 mj = *(const float4*)(ckb + 28*NTOK);
            av.x += 100000.0f * fmaf(mi, mj.x, -1.0f);
            av.y += 100000.0f * fmaf(mi, mj.y, -1.0f);
            av.z += 100000.0f * fmaf(mi, mj.z, -1.0f);
            av.w += 100000.0f * fmaf(mi, mj.w, -1.0f);
            float4 cur = *(const float4*)(a_sh + w*512 + j);
            cur.x += av.x; cur.y += av.y; cur.z += av.z; cur.w += av.w;
            *(float4*)(a_sh + w*512 + j) = cur;
        }
    }
    __syncthreads();

    // ---- Phase 2: softmax (warp w -> head w) ----
    {
        float* row = a_sh + w * 512;
        float mx = -1e30f;
        for (int j = lane; j < 512; j += 32) mx = fmaxf(mx, row[j]);
        #pragma unroll
        for (int o = 16; o; o >>= 1) mx = fmaxf(mx, __shfl_xor_sync(0xffffffffu, mx, o));
        float ssum = 0.f;
        for (int j = lane; j < 512; j += 32) { float e = __expf(row[j] - mx); row[j] = e; ssum += e; }
        #pragma unroll
        for (int o = 16; o; o >>= 1) ssum += __shfl_xor_sync(0xffffffffu, ssum, o);
        float inv = 1.0f / ssum;
        for (int j = lane; j < 512; j += 32) row[j] *= inv;
    }
    __syncthreads();

    // ---- Phase 3a: o and raw o_pt — 4 outputs per warp-task ----
    {
        float* optbuf = zsh;                       // 288 floats (z dead)
        #pragma unroll 2
        for (int r = 0; r < 10; r++) {
            const int task = r*12 + w;             // 120 tasks
            const int h = task / 10, dq = (task - h*10) * 4;
            const float* vb = g_vall + (size_t)(h*40 + dq)*NTOK;
            const float* ab = a_sh + h*512;
            float4 acc0, acc1, acc2, acc3;
            acc0.x=acc0.y=acc0.z=acc0.w=0.f; acc1=acc0; acc2=acc0; acc3=acc0;
            #pragma unroll
            for (int it = 0; it < 4; it++) {
                const int j = it*128 + lane*4;
                float4 a4 = *(const float4*)(ab + j);
                float4 v0 = *(const float4*)(vb + 0*NTOK + j);
                float4 v1 = *(const float4*)(vb + 1*NTOK + j);
                float4 v2 = *(const float4*)(vb + 2*NTOK + j);
                float4 v3 = *(const float4*)(vb + 3*NTOK + j);
                acc0.x += a4.x*v0.x; acc0.y += a4.y*v0.y; acc0.z += a4.z*v0.z; acc0.w += a4.w*v0.w;
                acc1.x += a4.x*v1.x; acc1.y += a4.y*v1.y; acc1.z += a4.z*v1.z; acc1.w += a4.w*v1.w;
                acc2.x += a4.x*v2.x; acc2.y += a4.y*v2.y; acc2.z += a4.z*v2.z; acc2.w += a4.w*v2.w;
                acc3.x += a4.x*v3.x; acc3.y += a4.y*v3.y; acc3.z += a4.z*v3.z; acc3.w += a4.w*v3.w;
            }
            float s0 = acc0.x + acc0.y + acc0.z + acc0.w;
            float s1 = acc1.x + acc1.y + acc1.z + acc1.w;
            float s2 = acc2.x + acc2.y + acc2.z + acc2.w;
            float s3 = acc3.x + acc3.y + acc3.z + acc3.w;
            #pragma unroll
            for (int o = 16; o; o >>= 1) {
                s0 += __shfl_xor_sync(0xffffffffu, s0, o);
                s1 += __shfl_xor_sync(0xffffffffu, s1, o);
                s2 += __shfl_xor_sync(0xffffffffu, s2, o);
                s3 += __shfl_xor_sync(0xffffffffu, s3, o);
            }
            if (lane == 0) {
                float res[4] = {s0, s1, s2, s3};
                #pragma unroll
                for (int dd = 0; dd < 4; dd++) {
                    int d = dq + dd;
                    if (d < 16) g_cat[i*CATD + h*16 + d] = res[dd];
                    else        optbuf[h*24 + (d - 16)] = res[dd];
                }
            }
        }
    }
    __syncthreads();

    // ---- Phase 3b: inverse rigid transform + norms ----
    if (t < 96) {
        const float* optbuf = zsh;
        float gx = optbuf[t*3], gy = optbuf[t*3 + 1], gz = optbuf[t*3 + 2];
        const float* R = tr + i*9; const float* T = tt + i*3;
        float dx = gx - T[0], dy = gy - T[1], dz = gz - T[2];
        float lx = R[0]*dx + R[3]*dy + R[6]*dz;
        float ly = R[1]*dx + R[4]*dy + R[7]*dz;
        float lz = R[2]*dx + R[5]*dy + R[8]*dz;
        float* cr = g_cat + i*CATD;
        cr[192 + t] = lx; cr[288 + t] = ly; cr[384 + t] = lz;
        cr[480 + t] = sqrtf(lx*lx + ly*ly + lz*lz + 1e-8f);
    }

    // ---- Phase 3c: o_pair with 4c x 4h register tile (z direct from L2) ----
    {
        const int cq4 = t & 31;                  // c-quad
        const int hg  = w % 3, js = w / 3;       // js: j-split 0..3
        float acc[4][4];                          // [hh][cc]
        #pragma unroll
        for (int a = 0; a < 4; a++)
            #pragma unroll
            for (int b = 0; b < 4; b++) acc[a][b] = 0.f;
        #pragma unroll 2
        for (int jqq = 0; jqq < 32; jqq++) {
            const int j = js*128 + jqq*4;
            float4 z4[4], a4[4];
            #pragma unroll
            for (int jj = 0; jj < 4; jj++)
                z4[jj] = *(const float4*)(z + zbase + (size_t)(j + jj)*128 + cq4*4);
            #pragma unroll
            for (int hh = 0; hh < 4; hh++)
                a4[hh] = *(const float4*)(a_sh + (hg*4 + hh)*512 + j);
            #pragma unroll
            for (int hh = 0; hh < 4; hh++) {
                acc[hh][0] += a4[hh].x*z4[0].x + a4[hh].y*z4[1].x + a4[hh].z*z4[2].x + a4[hh].w*z4[3].x;
                acc[hh][1] += a4[hh].x*z4[0].y + a4[hh].y*z4[1].y + a4[hh].z*z4[2].y + a4[hh].w*z4[3].y;
                acc[hh][2] += a4[hh].x*z4[0].z + a4[hh].y*z4[1].z + a4[hh].z*z4[2].z + a4[hh].w*z4[3].z;
                acc[hh][3] += a4[hh].x*z4[0].w + a4[hh].y*z4[1].w + a4[hh].z*z4[2].w + a4[hh].w*z4[3].w;
            }
        }
        float* part = zsh + 512;                 // [4js][12h][128c] = 6144 floats
        #pragma unroll
        for (int hh = 0; hh < 4; hh++)
            #pragma unroll
            for (int cc = 0; cc < 4; cc++)
                part[js*1536 + (hg*4 + hh)*128 + cq4*4 + cc] = acc[hh][cc];
    }
    __syncthreads();
    {
        const float* part = zsh + 512;
        for (int idx = t; idx < 1536; idx += 384) {
            float v = part[idx] + part[1536 + idx] + part[3072 + idx] + part[4608 + idx];
            g_cat[i*CATD + 576 + idx] = v;
        }
    }
}

// =================================================================================
// Kernel C1: out += cat @ Wout as tiled SGEMM. 64x64 tiles, BK=16,
// k-split 11 (192 each): grid = 8m x 6n x 11k = 528 blocks, 256 threads.
// =================================================================================
__global__ __launch_bounds__(256) void out_gemm_kernel(
    const float* __restrict__ Wout, float* __restrict__ out)
{
    __shared__ float ash[16 * 68];   // [kk][mm]
    __shared__ float bsh[16 * 68];   // [kk][nn]
    const int bx = blockIdx.x;
    const int ksp = bx / 48, rem = bx - ksp * 48;
    const int bm = rem & 7, bn = rem >> 3;
    const int m0 = bm * 64, n0 = bn * 64, kbase = ksp * 192;
    const int tid = threadIdx.x;
    const int tx = tid & 15, ty = tid >> 4;

    float pa[4], pb[4];
    #pragma unroll
    for (int r = 0; r < 4; r++) {
        int idx = tid + 256*r;
        int mm = idx >> 4, kk = idx & 15;
        pa[r] = g_cat[(size_t)(m0 + mm)*CATD + kbase + kk];
        int nn = idx & 63, kk2 = idx >> 6;
        pb[r] = Wout[(size_t)(kbase + kk2)*384 + n0 + nn];
    }

    float acc[4][4];
    #pragma unroll
    for (int a = 0; a < 4; a++)
        #pragma unroll
        for (int b = 0; b < 4; b++) acc[a][b] = 0.f;

    for (int k0 = 0; k0 < 192; k0 += 16) {
        __syncthreads();
        #pragma unroll
        for (int r = 0; r < 4; r++) {
            int idx = tid + 256*r;
            ash[(idx & 15)*68 + (idx >> 4)] = pa[r];
            bsh[(idx >> 6)*68 + (idx & 63)] = pb[r];
        }
        __syncthreads();
        if (k0 + 16 < 192) {
            #pragma unroll
            for (int r = 0; r < 4; r++) {
                int idx = tid + 256*r;
                int mm = idx >> 4, kk = idx & 15;
                pa[r] = g_cat[(size_t)(m0 + mm)*CATD + kbase + k0 + 16 + kk];
                int nn = idx & 63, kk2 = idx >> 6;
                pb[r] = Wout[(size_t)(kbase + k0 + 16 + kk2)*384 + n0 + nn];
            }
        }
        #pragma unroll
        for (int kk = 0; kk < 16; kk++) {
            float4 a4 = *(const float4*)(ash + kk*68 + ty*4);
            float4 b4 = *(const float4*)(bsh + kk*68 + tx*4);
            acc[0][0] += a4.x*b4.x; acc[0][1] += a4.x*b4.y; acc[0][2] += a4.x*b4.z; acc[0][3] += a4.x*b4.w;
            acc[1][0] += a4.y*b4.x; acc[1][1] += a4.y*b4.y; acc[1][2] += a4.y*b4.z; acc[1][3] += a4.y*b4.w;
            acc[2][0] += a4.z*b4.x; acc[2][1] += a4.z*b4.y; acc[2][2] += a4.z*b4.z; acc[2][3] += a4.z*b4.w;
            acc[3][0] += a4.w*b4.x; acc[3][1] += a4.w*b4.y; acc[3][2] += a4.w*b4.z; acc[3][3] += a4.w*b4.w;
        }
    }
    #pragma unroll
    for (int mi = 0; mi < 4; mi++) {
        float* op = out + (size_t)(m0 + ty*4 + mi)*384 + n0 + tx*4;
        atomicAdd(op + 0, acc[mi][0]);
        atomicAdd(op + 1, acc[mi][1]);
        atomicAdd(op + 2, acc[mi][2]);
        atomicAdd(op + 3, acc[mi][3]);
    }
}

// =================================================================================
extern "C" void kernel_launch(void* const* d_in, const int* in_sizes, int n_in,
                              void* d_out, int out_size)
{
    (void)in_sizes; (void)n_in; (void)out_size;
    const float* s    = (const float*)d_in[0];
    const float* z    = (const float*)d_in[1];
    const float* tt   = (const float*)d_in[2];
    const float* tr   = (const float*)d_in[3];
    const float* mask = (const float*)d_in[4];
    const float* Wq   = (const float*)d_in[5];
    const float* bq   = (const float*)d_in[6];
    const float* Wkv  = (const float*)d_in[7];
    const float* bkv  = (const float*)d_in[8];
    const float* Wqp  = (const float*)d_in[9];
    const float* bqp  = (const float*)d_in[10];
    const float* Wkvp = (const float*)d_in[11];
    const float* bkvp = (const float*)d_in[12];
    const float* Wb   = (const float*)d_in[13];
    const float* bb   = (const float*)d_in[14];
    const float* hwts = (const float*)d_in[15];
    const float* Wout = (const float*)d_in[16];
    const float* bout = (const float*)d_in[17];
    float* out = (float*)d_out;

    cudaFuncSetAttribute(attn_kernel, cudaFuncAttributeMaxDynamicSharedMemorySize, SMEM_BYTES);

    // attn stays at launch index 3 for the ncu capture
    pack_kernel<<<1728, 256>>>(Wq, bq, Wkv, bkv, Wqp, bqp, Wkvp, bkvp, Wb, bb, bout, out);
    sgemm_kernel<<<144, 256>>>(s);
    epi_kernel<<<128, 384>>>(tt, tr, mask);
    attn_kernel<<<512, 384, SMEM_BYTES>>>(z, mask, hwts, tt, tr);
    out_gemm_kernel<<<528, 256>>>(Wout, out);
}

// round 15
// speedup vs baseline: 1.1142x; 1.0643x over previous
#include <cuda_runtime.h>
#include <math.h>
#include <cstdint>

#define NTOK 512
#define H    12
#define CZ   128
#define CS   384
#define CATD 2112   // 192 + 96*4 + 1536 = 22*96
#define NOUT 1152   // packed projection width: Wq 192 | Wkv 384 | Wqp 144 | Wkvp 432

// ---------------- scratch (device globals) ----------------
__device__ float g_q   [NTOK * 192];         // [n][h*16+c]
__device__ float g_qpts[NTOK * 144];         // [n][(h*4+p)*3 + x]  (global frame)
__device__ float g_ck  [12 * 30 * NTOK];     // [h][d][n] d: 0-15 k, 16-27 kpts, 28 mask
__device__ float g_vall[12 * 40 * NTOK];     // [h][d][n] d: 0-15 v, 16-39 vpts
__device__ float g_cat [NTOK * CATD];
__device__ float g_wbt [12 * 132];           // c2*Wb^T [h][kk] (holes zero)
__device__ float g_ccn [12];                 // c2*bb
__device__ float g_wpack[CS * NOUT];         // [k][o] packed weights
__device__ float g_raw [NTOK * NOUT];        // raw projections (bias pre-init by pack)

// ---------------- cp.async helpers ----------------
__device__ __forceinline__ void cpasync16(unsigned int dst, const void* src) {
    asm volatile("cp.async.ca.shared.global [%0], [%1], 16;" :: "r"(dst), "l"(src));
}
__device__ __forceinline__ void cpasync_commit() {
    asm volatile("cp.async.commit_group;");
}
template <int N>
__device__ __forceinline__ void cpasync_wait() {
    asm volatile("cp.async.wait_group %0;" :: "n"(N));
}

// =================================================================================
// Kernel P: pack weights + c2*Wb^T + init out=bout + init g_raw=bias (2304 x 256)
// =================================================================================
__global__ __launch_bounds__(256) void pack_kernel(
    const float* __restrict__ Wq, const float* __restrict__ bq,
    const float* __restrict__ Wkv,const float* __restrict__ bkv,
    const float* __restrict__ Wqp,const float* __restrict__ bqp,
    const float* __restrict__ Wkvp,const float* __restrict__ bkvp,
    const float* __restrict__ Wb, const float* __restrict__ bb,
    const float* __restrict__ bout, float* __restrict__ out)
{
    const int idx = blockIdx.x * 256 + threadIdx.x;
    const float c2 = 0.57735026918962584f;   // 1/sqrt(3)
    if (idx < CS * NOUT) {
        int k = idx / NOUT, o = idx - k * NOUT;
        float v;
        if      (o < 192) v = Wq  [k*192 + o];
        else if (o < 576) v = Wkv [k*384 + o - 192];
        else if (o < 720) v = Wqp [k*144 + o - 576];
        else              v = Wkvp[k*432 + o - 720];
        g_wpack[idx] = v;
    }
    if (idx < NTOK * NOUT) {                 // g_raw pre-init with packed bias
        int o = idx % NOUT; float v;
        if      (o < 192) v = bq  [o];
        else if (o < 576) v = bkv [o - 192];
        else if (o < 720) v = bqp [o - 576];
        else              v = bkvp[o - 720];
        g_raw[idx] = v;
    }
    if (idx < 12 * 132) {
        int h = idx / 132, kk = idx - h * 132;
        g_wbt[idx] = (kk < 128) ? c2 * Wb[kk*12 + h] : 0.f;
    }
    if (idx < 12) g_ccn[idx] = c2 * bb[idx];
    if (idx < NTOK * 384) {
        out[idx] = bout[idx % 384];
    }
}

// =================================================================================
// Kernel A1: projection SGEMM  g_raw += s @ g_wpack (k-split 2, atomics).
// grid = 2 ksplit x 8 m x 18 n = 288 blocks, 256 threads.
// =================================================================================
__global__ __launch_bounds__(256) void sgemm_kernel(const float* __restrict__ s)
{
    __shared__ float ash[16 * 68];   // [kk][mm]
    __shared__ float bsh[16 * 68];   // [kk][nn]
    const int bx = blockIdx.x;
    const int ksp = bx / 144, rem = bx - ksp * 144;
    const int bm = rem & 7, bn = rem >> 3;
    const int m0 = bm * 64, n0 = bn * 64, kbase = ksp * 192;
    const int tid = threadIdx.x;
    const int tx = tid & 15, ty = tid >> 4;

    float pa[4], pb[4];
    #pragma unroll
    for (int r = 0; r < 4; r++) {
        int idx = tid + 256*r;
        int mm = idx >> 4, kk = idx & 15;
        pa[r] = s[(m0 + mm)*CS + kbase + kk];
        int nn = idx & 63, kk2 = idx >> 6;
        pb[r] = g_wpack[(kbase + kk2)*NOUT + n0 + nn];
    }

    float acc[4][4];
    #pragma unroll
    for (int a = 0; a < 4; a++)
        #pragma unroll
        for (int b = 0; b < 4; b++) acc[a][b] = 0.f;

    for (int k0 = 0; k0 < 192; k0 += 16) {
        __syncthreads();
        #pragma unroll
        for (int r = 0; r < 4; r++) {
            int idx = tid + 256*r;
            ash[(idx & 15)*68 + (idx >> 4)] = pa[r];
            bsh[(idx >> 6)*68 + (idx & 63)] = pb[r];
        }
        __syncthreads();
        if (k0 + 16 < 192) {
            #pragma unroll
            for (int r = 0; r < 4; r++) {
                int idx = tid + 256*r;
                int mm = idx >> 4, kk = idx & 15;
                pa[r] = s[(m0 + mm)*CS + kbase + k0 + 16 + kk];
                int nn = idx & 63, kk2 = idx >> 6;
                pb[r] = g_wpack[(kbase + k0 + 16 + kk2)*NOUT + n0 + nn];
            }
        }
        #pragma unroll
        for (int kk = 0; kk < 16; kk++) {
            float4 a4 = *(const float4*)(ash + kk*68 + ty*4);
            float4 b4 = *(const float4*)(bsh + kk*68 + tx*4);
            acc[0][0] += a4.x*b4.x; acc[0][1] += a4.x*b4.y; acc[0][2] += a4.x*b4.z; acc[0][3] += a4.x*b4.w;
            acc[1][0] += a4.y*b4.x; acc[1][1] += a4.y*b4.y; acc[1][2] += a4.y*b4.z; acc[1][3] += a4.y*b4.w;
            acc[2][0] += a4.z*b4.x; acc[2][1] += a4.z*b4.y; acc[2][2] += a4.z*b4.z; acc[2][3] += a4.z*b4.w;
            acc[3][0] += a4.w*b4.x; acc[3][1] += a4.w*b4.y; acc[3][2] += a4.w*b4.z; acc[3][3] += a4.w*b4.w;
        }
    }
    #pragma unroll
    for (int mi = 0; mi < 4; mi++) {
        float* op = g_raw + (size_t)(m0 + ty*4 + mi)*NOUT + n0 + tx*4;
        atomicAdd(op + 0, acc[mi][0]);
        atomicAdd(op + 1, acc[mi][1]);
        atomicAdd(op + 2, acc[mi][2]);
        atomicAdd(op + 3, acc[mi][3]);
    }
}

// =================================================================================
// Kernel A2: epilogue — rigid transform + scatter. 512 blocks, 1 token each.
// =================================================================================
__global__ __launch_bounds__(384) void epi_kernel(
    const float* __restrict__ tt, const float* __restrict__ tr, const float* __restrict__ msk)
{
    const int n = blockIdx.x;
    const int t = threadIdx.x;
    const float* raw = g_raw + (size_t)n * NOUT;

    if (t < 192) {
        int h = t >> 4, c = t & 15;
        g_q[n*192 + t] = raw[t];
        g_ck  [(h*30 + c)*NTOK + n] = raw[192 + h*32 + c];        // k
        g_vall[(h*40 + c)*NTOK + n] = raw[192 + h*32 + 16 + c];   // v
    } else if (t < 240) {
        int p = t - 192;   // (h*4 + pq)
        float lx = raw[576 + p], ly = raw[576 + 48 + p], lz = raw[576 + 96 + p];
        const float* R = tr + n*9; const float* T = tt + n*3;
        float gx = R[0]*lx + R[1]*ly + R[2]*lz + T[0];
        float gy = R[3]*lx + R[4]*ly + R[5]*lz + T[1];
        float gz = R[6]*lx + R[7]*ly + R[8]*lz + T[2];
        g_qpts[n*144 + p*3 + 0] = gx;
        g_qpts[n*144 + p*3 + 1] = gy;
        g_qpts[n*144 + p*3 + 2] = gz;
    } else {
        int p = t - 240;   // (h*12 + pp)
        float lx = raw[720 + p], ly = raw[720 + 144 + p], lz = raw[720 + 288 + p];
        const float* R = tr + n*9; const float* T = tt + n*3;
        float gx = R[0]*lx + R[1]*ly + R[2]*lz + T[0];
        float gy = R[3]*lx + R[4]*ly + R[5]*lz + T[1];
        float gz = R[6]*lx + R[7]*ly + R[8]*lz + T[2];
        int h = p / 12, pp = p - h*12;
        if (pp < 4) {
            int d = 16 + pp*3;
            g_ck[(h*30 + d + 0)*NTOK + n] = gx;
            g_ck[(h*30 + d + 1)*NTOK + n] = gy;
            g_ck[(h*30 + d + 2)*NTOK + n] = gz;
        } else {
            int d = 16 + (pp - 4)*3;
            g_vall[(h*40 + d + 0)*NTOK + n] = gx;
            g_vall[(h*40 + d + 1)*NTOK + n] = gy;
            g_vall[(h*40 + d + 2)*NTOK + n] = gz;
        }
    }
    if (t < 12) {
        g_ck[(t*30 + 28)*NTOK + n] = msk[n];
    }
}

// =================================================================================
// Kernel B: fused attention — EXACT R14/R10 structure (155us, regs 73). UNCHANGED.
// =================================================================================
#define ASHO 0                 // a[12][512]                       6144
#define ZSHO 6144              // z ping-pong 2x[64][132]=16896    (reused later)
#define WBTO 23040             // c2*Wb^T [12][132]                1584
#define CQSO 24624             // cq [12][32]                      384
#define CCNO 25008             // cconst[12]
#define SMEM_FLOATS 25024
#define SMEM_BYTES  (SMEM_FLOATS * 4)

__global__ __launch_bounds__(384) void attn_kernel(
    const float* __restrict__ z,   const float* __restrict__ msk,
    const float* __restrict__ hwts,const float* __restrict__ tt,
    const float* __restrict__ tr)
{
    extern __shared__ float sm[];
    float* a_sh = sm + ASHO;
    float* zsh  = sm + ZSHO;
    float* wbt  = sm + WBTO;
    float* cqs  = sm + CQSO;
    float* ccn  = sm + CCNO;

    const int i = blockIdx.x, t = threadIdx.x;
    const float mask_i = msk[i];

    // ---- build cq / cconst / wbt ----
    for (int idx = t; idx < 360; idx += 384) {
        int h = idx / 30, d = idx - h*30;
        float x = hwts[h];
        float sp = (x > 20.f) ? x : log1pf(__expf(x));
        float hw = sp * 0.13608276348795434f;   // softplus * sqrt(1/54)
        float v;
        if      (d < 16)  v = 0.14433756729740643f * g_q[i*192 + h*16 + d]; // 1/sqrt(48)
        else if (d < 28)  v = g_qpts[i*144 + h*12 + (d - 16)];              // raw q_pts
        else if (d == 28) v = -0.5f * hw;
        else              v = mask_i;
        cqs[h*32 + d] = v;
    }
    if (t < 12) ccn[t] = g_ccn[t];
    for (int idx = t; idx < 1584; idx += 384)
        wbt[idx] = g_wbt[idx];
    __syncthreads();

    const size_t zbase = (size_t)i * NTOK * CZ;
    const unsigned int zsh_s = (unsigned int)__cvta_generic_to_shared(zsh);
    const int w = t >> 5, lane = t & 31;

    // ---- Phase 1: bias GEMM with cp.async double-buffered 64-row chunks ----
    {
        const int ks = t & 7, g = t >> 3;         // 8 k-splits, 48 groups
        const int hg = g % 3, jq = g / 3;         // jq 0..15, hg: 4-head group

        // stage chunk 0 into buf 0
        for (int idx = t; idx < 2048; idx += 384) {
            int r = idx >> 5, c4 = idx & 31;
            cpasync16(zsh_s + (r*132 + c4*4)*4, z + zbase + (size_t)r*128 + c4*4);
        }
        cpasync_commit();

        for (int c = 0; c < 8; c++) {
            const float* curbuf = zsh + (c & 1) * 8448;
            if (c < 7) {
                const unsigned int nb_s = zsh_s + (((c + 1) & 1) * 8448) * 4;
                const int j0n = (c + 1) * 64;
                for (int idx = t; idx < 2048; idx += 384) {
                    int r = idx >> 5, c4 = idx & 31;
                    cpasync16(nb_s + (r*132 + c4*4)*4, z + zbase + (size_t)(j0n + r)*128 + c4*4);
                }
                cpasync_commit();
                cpasync_wait<1>();
            } else {
                cpasync_wait<0>();
            }
            __syncthreads();

            const int j0 = c * 64;
            float acc[4][4];
            #pragma unroll
            for (int a = 0; a < 4; a++)
                #pragma unroll
                for (int b = 0; b < 4; b++) acc[a][b] = 0.f;
            #pragma unroll
            for (int it = 0; it < 4; it++) {
                const int kq = it*8 + ks;
                float4 z4[4], w4[4];
                #pragma unroll
                for (int jj = 0; jj < 4; jj++)
                    z4[jj] = *(const float4*)(curbuf + (jq*4 + jj)*132 + kq*4);
                #pragma unroll
                for (int hh = 0; hh < 4; hh++)
                    w4[hh] = *(const float4*)(wbt + (hg*4 + hh)*132 + kq*4);
                #pragma unroll
                for (int jj = 0; jj < 4; jj++)
                    #pragma unroll
                    for (int hh = 0; hh < 4; hh++) {
                        acc[jj][hh] += z4[jj].x * w4[hh].x;
                        acc[jj][hh] += z4[jj].y * w4[hh].y;
                        acc[jj][hh] += z4[jj].z * w4[hh].z;
                        acc[jj][hh] += z4[jj].w * w4[hh].w;
                    }
            }
            #pragma unroll
            for (int jj = 0; jj < 4; jj++)
                #pragma unroll
                for (int hh = 0; hh < 4; hh++) {
                    float v = acc[jj][hh];
                    v += __shfl_xor_sync(0xffffffffu, v, 1);
                    v += __shfl_xor_sync(0xffffffffu, v, 2);
                    v += __shfl_xor_sync(0xffffffffu, v, 4);
                    if (ks == 0)
                        a_sh[(hg*4 + hh)*512 + j0 + jq*4 + jj] = v;
                }
            __syncthreads();
        }
    }

    // ---- Phase 1b: add qk + point-dist (direct (q-k)^2) + mask ----
    {
        float cq[16], qp[12];
        #pragma unroll
        for (int d = 0; d < 16; d++) cq[d] = cqs[w*32 + d];
        #pragma unroll
        for (int p = 0; p < 12; p++) qp[p] = cqs[w*32 + 16 + p];
        const float nh = cqs[w*32 + 28];          // -0.5*hw
        const float mi = cqs[w*32 + 29];          // mask_i
        const float cst = ccn[w];
        #pragma unroll
        for (int r = 0; r < 4; r++) {
            const int j = r*128 + lane*4;
            const float* ckb = g_ck + (size_t)w*30*NTOK + j;
            float4 av; av.x = cst; av.y = cst; av.z = cst; av.w = cst;
            #pragma unroll
            for (int d = 0; d < 16; d++) {
                float4 kv = *(const float4*)(ckb + d*NTOK);
                av.x += cq[d]*kv.x; av.y += cq[d]*kv.y;
                av.z += cq[d]*kv.z; av.w += cq[d]*kv.w;
            }
            float4 d2; d2.x = d2.y = d2.z = d2.w = 0.f;
            #pragma unroll
            for (int p = 0; p < 12; p++) {
                float4 kv = *(const float4*)(ckb + (16 + p)*NTOK);
                float dx = qp[p] - kv.x; d2.x += dx*dx;
                float dy = qp[p] - kv.y; d2.y += dy*dy;
                float dz = qp[p] - kv.z; d2.z += dz*dz;
                float dw = qp[p] - kv.w; d2.w += dw*dw;
            }
            av.x += nh*d2.x; av.y += nh*d2.y; av.z += nh*d2.z; av.w += nh*d2.w;
            float4 mj = *(const float4*)(ckb + 28*NTOK);
            av.x += 100000.0f * fmaf(mi, mj.x, -1.0f);
            av.y += 100000.0f * fmaf(mi, mj.y, -1.0f);
            av.z += 100000.0f * fmaf(mi, mj.z, -1.0f);
            av.w += 100000.0f * fmaf(mi, mj.w, -1.0f);
            float4 cur = *(const float4*)(a_sh + w*512 + j);
            cur.x += av.x; cur.y += av.y; cur.z += av.z; cur.w += av.w;
            *(float4*)(a_sh + w*512 + j) = cur;
        }
    }
    __syncthreads();

    // ---- Phase 2: softmax (warp w -> head w) ----
    {
        float* row = a_sh + w * 512;
        float mx = -1e30f;
        for (int j = lane; j < 512; j += 32) mx = fmaxf(mx, row[j]);
        #pragma unroll
        for (int o = 16; o; o >>= 1) mx = fmaxf(mx, __shfl_xor_sync(0xffffffffu, mx, o));
        float ssum = 0.f;
        for (int j = lane; j < 512; j += 32) { float e = __expf(row[j] - mx); row[j] = e; ssum += e; }
        #pragma unroll
        for (int o = 16; o; o >>= 1) ssum += __shfl_xor_sync(0xffffffffu, ssum, o);
        float inv = 1.0f / ssum;
        for (int j = lane; j < 512; j += 32) row[j] *= inv;
    }
    __syncthreads();

    // ---- Phase 3a: o and raw o_pt — 4 outputs per warp-task ----
    {
        float* optbuf = zsh;                       // 288 floats (z dead)
        #pragma unroll 2
        for (int r = 0; r < 10; r++) {
            const int task = r*12 + w;             // 120 tasks
            const int h = task / 10, dq = (task - h*10) * 4;
            const float* vb = g_vall + (size_t)(h*40 + dq)*NTOK;
            const float* ab = a_sh + h*512;
            float4 acc0, acc1, acc2, acc3;
            acc0.x=acc0.y=acc0.z=acc0.w=0.f; acc1=acc0; acc2=acc0; acc3=acc0;
            #pragma unroll
            for (int it = 0; it < 4; it++) {
                const int j = it*128 + lane*4;
                float4 a4 = *(const float4*)(ab + j);
                float4 v0 = *(const float4*)(vb + 0*NTOK + j);
                float4 v1 = *(const float4*)(vb + 1*NTOK + j);
                float4 v2 = *(const float4*)(vb + 2*NTOK + j);
                float4 v3 = *(const float4*)(vb + 3*NTOK + j);
                acc0.x += a4.x*v0.x; acc0.y += a4.y*v0.y; acc0.z += a4.z*v0.z; acc0.w += a4.w*v0.w;
                acc1.x += a4.x*v1.x; acc1.y += a4.y*v1.y; acc1.z += a4.z*v1.z; acc1.w += a4.w*v1.w;
                acc2.x += a4.x*v2.x; acc2.y += a4.y*v2.y; acc2.z += a4.z*v2.z; acc2.w += a4.w*v2.w;
                acc3.x += a4.x*v3.x; acc3.y += a4.y*v3.y; acc3.z += a4.z*v3.z; acc3.w += a4.w*v3.w;
            }
            float s0 = acc0.x + acc0.y + acc0.z + acc0.w;
            float s1 = acc1.x + acc1.y + acc1.z + acc1.w;
            float s2 = acc2.x + acc2.y + acc2.z + acc2.w;
            float s3 = acc3.x + acc3.y + acc3.z + acc3.w;
            #pragma unroll
            for (int o = 16; o; o >>= 1) {
                s0 += __shfl_xor_sync(0xffffffffu, s0, o);
                s1 += __shfl_xor_sync(0xffffffffu, s1, o);
                s2 += __shfl_xor_sync(0xffffffffu, s2, o);
                s3 += __shfl_xor_sync(0xffffffffu, s3, o);
            }
            if (lane == 0) {
                float res[4] = {s0, s1, s2, s3};
                #pragma unroll
                for (int dd = 0; dd < 4; dd++) {
                    int d = dq + dd;
                    if (d < 16) g_cat[i*CATD + h*16 + d] = res[dd];
                    else        optbuf[h*24 + (d - 16)] = res[dd];
                }
            }
        }
    }
    __syncthreads();

    // ---- Phase 3b: inverse rigid transform + norms ----
    if (t < 96) {
        const float* optbuf = zsh;
        float gx = optbuf[t*3], gy = optbuf[t*3 + 1], gz = optbuf[t*3 + 2];
        const float* R = tr + i*9; const float* T = tt + i*3;
        float dx = gx - T[0], dy = gy - T[1], dz = gz - T[2];
        float lx = R[0]*dx + R[3]*dy + R[6]*dz;
        float ly = R[1]*dx + R[4]*dy + R[7]*dz;
        float lz = R[2]*dx + R[5]*dy + R[8]*dz;
        float* cr = g_cat + i*CATD;
        cr[192 + t] = lx; cr[288 + t] = ly; cr[384 + t] = lz;
        cr[480 + t] = sqrtf(lx*lx + ly*ly + lz*lz + 1e-8f);
    }

    // ---- Phase 3c: o_pair with 4c x 4h register tile (z direct from L2) ----
    {
        const int cq4 = t & 31;                  // c-quad
        const int hg  = w % 3, js = w / 3;       // js: j-split 0..3
        float acc[4][4];                          // [hh][cc]
        #pragma unroll
        for (int a = 0; a < 4; a++)
            #pragma unroll
            for (int b = 0; b < 4; b++) acc[a][b] = 0.f;
        #pragma unroll 2
        for (int jqq = 0; jqq < 32; jqq++) {
            const int j = js*128 + jqq*4;
            float4 z4[4], a4[4];
            #pragma unroll
            for (int jj = 0; jj < 4; jj++)
                z4[jj] = *(const float4*)(z + zbase + (size_t)(j + jj)*128 + cq4*4);
            #pragma unroll
            for (int hh = 0; hh < 4; hh++)
                a4[hh] = *(const float4*)(a_sh + (hg*4 + hh)*512 + j);
            #pragma unroll
            for (int hh = 0; hh < 4; hh++) {
                acc[hh][0] += a4[hh].x*z4[0].x + a4[hh].y*z4[1].x + a4[hh].z*z4[2].x + a4[hh].w*z4[3].x;
                acc[hh][1] += a4[hh].x*z4[0].y + a4[hh].y*z4[1].y + a4[hh].z*z4[2].y + a4[hh].w*z4[3].y;
                acc[hh][2] += a4[hh].x*z4[0].z + a4[hh].y*z4[1].z + a4[hh].z*z4[2].z + a4[hh].w*z4[3].z;
                acc[hh][3] += a4[hh].x*z4[0].w + a4[hh].y*z4[1].w + a4[hh].z*z4[2].w + a4[hh].w*z4[3].w;
            }
        }
        float* part = zsh + 512;                 // [4js][12h][128c] = 6144 floats
        #pragma unroll
        for (int hh = 0; hh < 4; hh++)
            #pragma unroll
            for (int cc = 0; cc < 4; cc++)
                part[js*1536 + (hg*4 + hh)*128 + cq4*4 + cc] = acc[hh][cc];
    }
    __syncthreads();
    {
        const float* part = zsh + 512;
        for (int idx = t; idx < 1536; idx += 384) {
            float v = part[idx] + part[1536 + idx] + part[3072 + idx] + part[4608 + idx];
            g_cat[i*CATD + 576 + idx] = v;
        }
    }
}

// =================================================================================
// Kernel C1: out += cat @ Wout as tiled SGEMM. 64x64 tiles, BK=16,
// k-split 22 (96 each): grid = 22k x 8m x 6n = 1056 blocks, 256 threads.
// =================================================================================
__global__ __launch_bounds__(256) void out_gemm_kernel(
    const float* __restrict__ Wout, float* __restrict__ out)
{
    __shared__ float ash[16 * 68];   // [kk][mm]
    __shared__ float bsh[16 * 68];   // [kk][nn]
    const int bx = blockIdx.x;
    const int ksp = bx / 48, rem = bx - ksp * 48;
    const int bm = rem & 7, bn = rem >> 3;
    const int m0 = bm * 64, n0 = bn * 64, kbase = ksp * 96;
    const int tid = threadIdx.x;
    const int tx = tid & 15, ty = tid >> 4;

    float pa[4], pb[4];
    #pragma unroll
    for (int r = 0; r < 4; r++) {
        int idx = tid + 256*r;
        int mm = idx >> 4, kk = idx & 15;
        pa[r] = g_cat[(size_t)(m0 + mm)*CATD + kbase + kk];
        int nn = idx & 63, kk2 = idx >> 6;
        pb[r] = Wout[(size_t)(kbase + kk2)*384 + n0 + nn];
    }

    float acc[4][4];
    #pragma unroll
    for (int a = 0; a < 4; a++)
        #pragma unroll
        for (int b = 0; b < 4; b++) acc[a][b] = 0.f;

    for (int k0 = 0; k0 < 96; k0 += 16) {
        __syncthreads();
        #pragma unroll
        for (int r = 0; r < 4; r++) {
            int idx = tid + 256*r;
            ash[(idx & 15)*68 + (idx >> 4)] = pa[r];
            bsh[(idx >> 6)*68 + (idx & 63)] = pb[r];
        }
        __syncthreads();
        if (k0 + 16 < 96) {
            #pragma unroll
            for (int r = 0; r < 4; r++) {
                int idx = tid + 256*r;
                int mm = idx >> 4, kk = idx & 15;
                pa[r] = g_cat[(size_t)(m0 + mm)*CATD + kbase + k0 + 16 + kk];
                int nn = idx & 63, kk2 = idx >> 6;
                pb[r] = Wout[(size_t)(kbase + k0 + 16 + kk2)*384 + n0 + nn];
            }
        }
        #pragma unroll
        for (int kk = 0; kk < 16; kk++) {
            float4 a4 = *(const float4*)(ash + kk*68 + ty*4);
            float4 b4 = *(const float4*)(bsh + kk*68 + tx*4);
            acc[0][0] += a4.x*b4.x; acc[0][1] += a4.x*b4.y; acc[0][2] += a4.x*b4.z; acc[0][3] += a4.x*b4.w;
            acc[1][0] += a4.y*b4.x; acc[1][1] += a4.y*b4.y; acc[1][2] += a4.y*b4.z; acc[1][3] += a4.y*b4.w;
            acc[2][0] += a4.z*b4.x; acc[2][1] += a4.z*b4.y; acc[2][2] += a4.z*b4.z; acc[2][3] += a4.z*b4.w;
            acc[3][0] += a4.w*b4.x; acc[3][1] += a4.w*b4.y; acc[3][2] += a4.w*b4.z; acc[3][3] += a4.w*b4.w;
        }
    }
    #pragma unroll
    for (int mi = 0; mi < 4; mi++) {
        float* op = out + (size_t)(m0 + ty*4 + mi)*384 + n0 + tx*4;
        atomicAdd(op + 0, acc[mi][0]);
        atomicAdd(op + 1, acc[mi][1]);
        atomicAdd(op + 2, acc[mi][2]);
        atomicAdd(op + 3, acc[mi][3]);
    }
}

// =================================================================================
extern "C" void kernel_launch(void* const* d_in, const int* in_sizes, int n_in,
                              void* d_out, int out_size)
{
    (void)in_sizes; (void)n_in; (void)out_size;
    const float* s    = (const float*)d_in[0];
    const float* z    = (const float*)d_in[1];
    const float* tt   = (const float*)d_in[2];
    const float* tr   = (const float*)d_in[3];
    const float* mask = (const float*)d_in[4];
    const float* Wq   = (const float*)d_in[5];
    const float* bq   = (const float*)d_in[6];
    const float* Wkv  = (const float*)d_in[7];
    const float* bkv  = (const float*)d_in[8];
    const float* Wqp  = (const float*)d_in[9];
    const float* bqp  = (const float*)d_in[10];
    const float* Wkvp = (const float*)d_in[11];
    const float* bkvp = (const float*)d_in[12];
    const float* Wb   = (const float*)d_in[13];
    const float* bb   = (const float*)d_in[14];
    const float* hwts = (const float*)d_in[15];
    const float* Wout = (const float*)d_in[16];
    const float* bout = (const float*)d_in[17];
    float* out = (float*)d_out;

    cudaFuncSetAttribute(attn_kernel, cudaFuncAttributeMaxDynamicSharedMemorySize, SMEM_BYTES);

    // attn stays at launch index 3 for the ncu capture
    pack_kernel<<<2304, 256>>>(Wq, bq, Wkv, bkv, Wqp, bqp, Wkvp, bkvp, Wb, bb, bout, out);
    sgemm_kernel<<<288, 256>>>(s);
    epi_kernel<<<512, 384>>>(tt, tr, mask);
    attn_kernel<<<512, 384, SMEM_BYTES>>>(z, mask, hwts, tt, tr);
    out_gemm_kernel<<<1056, 256>>>(Wout, out);
}